// round 14
// baseline (speedup 1.0000x reference)
#include <cuda_runtime.h>
#include <cuda_pipeline.h>

#define F_IN   10000
#define F_PAD  10240     // padded to 40 groups of 256 columns
#define NROWS  4096
#define GROUPS 40        // column groups of 256
#define WARPS  4         // warps per block (one group each)
#define RB     32        // rows per block
#define CH     4         // rows per cp.async chunk (double-buffered)
#define NC     (RB / CH) // chunks per block (8)
#define NPART  (GROUPS * 8)          // 320 partials per row
#define L2E    1.4426950408889634f
#define LN2    0.6931471805599453f
#define HL2PI2 1.3257480647361593f   // 0.5*log2(2*pi)

// scratch (no allocations allowed)
__device__ float g_pp[F_PAD * 9];               // per-column [m][{-K, B, C_}] base-2 Horner params
__device__ float g_part[(size_t)NROWS * NPART]; // per-row partials, row-major

__device__ __forceinline__ float ex2(float x) {
    float r; asm("ex2.approx.ftz.f32 %0, %1;" : "=f"(r) : "f"(x)); return r;
}
__device__ __forceinline__ float lg2(float x) {
    float r; asm("lg2.approx.ftz.f32 %0, %1;" : "=f"(r) : "f"(x)); return r;
}

// Empty kernels: keep the ncu capture window (-s 5 -c 1) on spn_main.
__global__ void dummy_a_kernel() {}
__global__ void dummy_b_kernel() {}

// Kernel 1: one thread per (f, m). Folds w1 log-softmax, log(std), permutation
// into per-column base-2 Horner constants: t_m(x) = (-K x + B) x + C_.
// Pad columns contribute exactly 0: t0 = 0, t1 = t2 = -1e30 (garbage x is
// harmless there — enables unpredicated clamped loads in the main kernel).
__global__ void prep_kernel(const float* __restrict__ means,
                            const float* __restrict__ stds,
                            const float* __restrict__ w1,
                            const int*   __restrict__ idx) {
    int t = blockIdx.x * blockDim.x + threadIdx.x;
    int f = t / 3, m = t - f * 3;
    if (f >= F_PAD) return;
    if (f >= F_IN) {
        if (m == 0) {
            float* q = &g_pp[(size_t)f * 9];
            q[0]=0.f; q[1]=0.f; q[2]=0.f;
            q[3]=0.f; q[4]=0.f; q[5]=-1e30f;
            q[6]=0.f; q[7]=0.f; q[8]=-1e30f;
        }
        return;
    }
    float u0 = w1[f*3+0]*L2E, u1 = w1[f*3+1]*L2E, u2 = w1[f*3+2]*L2E;
    float mu = fmaxf(u0, fmaxf(u1, u2));
    float l2 = mu + lg2(ex2(u0-mu) + ex2(u1-mu) + ex2(u2-mu));  // log2 softmax denom
    float um   = (m == 0) ? u0 : (m == 1 ? u1 : u2);
    float mean = means[f*3+m];
    float sd   = stds[f*3+m];
    float K    = 0.7213475204444817f / (sd * sd);   // 0.5*log2(e)/sd^2
    float A    = (um - l2) - lg2(sd) - HL2PI2;
    float* q = &g_pp[(size_t)idx[f] * 9 + m * 3];
    q[0] = -K;
    q[1] = 2.0f * K * mean;
    q[2] = A - K * mean * mean;
}

// Kernel 2: warp owns 256 consecutive columns; lane owns TWO 4-col sub-blocks
// (at g*256 + lane*4 and +128) so each cp.async copy is a contiguous 512B
// warp transaction. Per-row fixed costs (LDS, butterfly, lg2, store, pipeline)
// now amortize over 256 columns: ~0.55 issue slots/col vs R13's 0.68.
// cp.async double-buffered 4-row chunks with compile-time buffer selection
// and hoisted output pointer (R13 structure). Per row: (a = sum mx,
// p = prod(1+s)) over 8 cols; 2-step butterfly, ONE lg2, lanes 0-7 store.
__global__ __launch_bounds__(WARPS * 32, 5) void spn_main(const float* __restrict__ x) {
    const int lane = threadIdx.x & 31;
    const int w    = threadIdx.x >> 5;
    const int g    = blockIdx.x * WARPS + w;      // column group 0..39
    const int r0   = blockIdx.y * RB;
    const int cb0  = g * 256 + lane * 4;          // sub-block 0
    const int cb1  = cb0 + 128;                   // sub-block 1

    // [warp][buffer][row-in-chunk][sub-block][lane]
    __shared__ float4 buf[WARPS][2][CH][2][32];

    float nk[8][3], pb[8][3], pc[8][3];
    #pragma unroll
    for (int c = 0; c < 8; c++) {
        const int col = (c < 4) ? (cb0 + c) : (cb1 + c - 4);
        const float* p = &g_pp[(size_t)col * 9];
        #pragma unroll
        for (int m = 0; m < 3; m++) {
            nk[c][m] = __ldg(p + m*3 + 0);
            pb[c][m] = __ldg(p + m*3 + 1);
            pc[c][m] = __ldg(p + m*3 + 2);
        }
    }
    // Clamp OOB lanes to a valid address; pad params zero their contribution.
    const int c0 = (cb0 < F_IN) ? cb0 : (F_IN - 4);
    const int c1 = (cb1 < F_IN) ? cb1 : (F_IN - 4);
    const float* gp0 = x + (size_t)r0 * F_IN + c0;
    const float* gp1 = x + (size_t)r0 * F_IN + c1;

    float4* s0 = &buf[w][0][0][0][lane];   // imm-offset addressing from here
    float4* s1 = &buf[w][1][0][0][lane];

    float* outp = g_part + (size_t)r0 * NPART + g * 8 + lane;
    const bool wr = (lane < 8);

    auto body = [&](float4 xv4a, float4 xv4b) {
        const float xa[8] = {xv4a.x, xv4a.y, xv4a.z, xv4a.w,
                             xv4b.x, xv4b.y, xv4b.z, xv4b.w};
        float a = 0.0f, p = 1.0f;
        #pragma unroll
        for (int c = 0; c < 8; c++) {
            float xv = xa[c];
            float t0 = fmaf(fmaf(xv, nk[c][0], pb[c][0]), xv, pc[c][0]);
            float t1 = fmaf(fmaf(xv, nk[c][1], pb[c][1]), xv, pc[c][1]);
            float t2 = fmaf(fmaf(xv, nk[c][2], pb[c][2]), xv, pc[c][2]);
            float hi = fmaxf(t0, t1), lo = fminf(t0, t1);
            float mx = fmaxf(hi, t2), md = fminf(hi, t2);
            float s  = ex2(md - mx) + ex2(lo - mx);
            a += mx;
            p = fmaf(s, p, p);     // p *= (1 + s); p <= 3^8 per lane
        }
        a += __shfl_xor_sync(0xffffffffu, a, 16);
        p *= __shfl_xor_sync(0xffffffffu, p, 16);
        a += __shfl_xor_sync(0xffffffffu, a, 8);
        p *= __shfl_xor_sync(0xffffffffu, p, 8);
        float v = a + lg2(p);      // p <= 3^32 ~ 1.8e15, no overflow
        if (wr) *outp = v;
        outp += NPART;
    };

    // slot index within a buffer: [i][j][lane] stride = 64 float4s per row i
    #define SLOT(base, i, j) ((base) + (i) * 64 + (j) * 32)

    // Prologue: chunk 0 -> buffer 0.
    #pragma unroll
    for (int i = 0; i < CH; i++) {
        __pipeline_memcpy_async(SLOT(s0, i, 0), gp0 + (size_t)i * F_IN, 16);
        __pipeline_memcpy_async(SLOT(s0, i, 1), gp1 + (size_t)i * F_IN, 16);
    }
    __pipeline_commit();
    gp0 += (size_t)CH * F_IN;  gp1 += (size_t)CH * F_IN;

    #pragma unroll 1
    for (int k = 0; k < NC; k += 2) {
        // Issue chunk k+1 -> buffer 1 (always exists: NC even).
        #pragma unroll
        for (int i = 0; i < CH; i++) {
            __pipeline_memcpy_async(SLOT(s1, i, 0), gp0 + (size_t)i * F_IN, 16);
            __pipeline_memcpy_async(SLOT(s1, i, 1), gp1 + (size_t)i * F_IN, 16);
        }
        gp0 += (size_t)CH * F_IN;  gp1 += (size_t)CH * F_IN;
        __pipeline_commit();
        __pipeline_wait_prior(1);       // chunk k ready in buffer 0
        #pragma unroll
        for (int i = 0; i < CH; i++) body(*SLOT(s0, i, 0), *SLOT(s0, i, 1));

        // Issue chunk k+2 -> buffer 0 (if it exists).
        if (k + 2 < NC) {
            #pragma unroll
            for (int i = 0; i < CH; i++) {
                __pipeline_memcpy_async(SLOT(s0, i, 0), gp0 + (size_t)i * F_IN, 16);
                __pipeline_memcpy_async(SLOT(s0, i, 1), gp1 + (size_t)i * F_IN, 16);
            }
            gp0 += (size_t)CH * F_IN;  gp1 += (size_t)CH * F_IN;
        }
        __pipeline_commit();            // (possibly empty group keeps counts aligned)
        __pipeline_wait_prior(1);       // chunk k+1 ready in buffer 1
        #pragma unroll
        for (int i = 0; i < CH; i++) body(*SLOT(s1, i, 0), *SLOT(s1, i, 1));
    }
    #undef SLOT
}

// Kernel 3: fold 320 partials per row (one warp per row, deterministic order).
__global__ void reduce_kernel(float* __restrict__ out) {
    const int lane = threadIdx.x & 31;
    const int n    = blockIdx.x * (blockDim.x >> 5) + (threadIdx.x >> 5);
    if (n >= NROWS) return;
    const float* p = &g_part[(size_t)n * NPART];
    float s = 0.0f;
    #pragma unroll
    for (int i = 0; i < NPART / 32; i++) s += p[lane + i * 32];
    #pragma unroll
    for (int off = 16; off; off >>= 1)
        s += __shfl_xor_sync(0xffffffffu, s, off);
    if (lane == 0) out[n] = s * LN2;
}

extern "C" void kernel_launch(void* const* d_in, const int* in_sizes, int n_in,
                              void* d_out, int out_size) {
    const float* x     = (const float*)d_in[0];
    const float* means = (const float*)d_in[1];
    const float* stds  = (const float*)d_in[2];
    const float* w1    = (const float*)d_in[3];
    // d_in[4..7] = w2..w5: provably no-ops (log_softmax over size-1 axis == 0)
    const int*   idx   = (const int*)d_in[8];

    prep_kernel<<<(F_PAD * 3 + 127) / 128, 128>>>(means, stds, w1, idx);
    dummy_a_kernel<<<1, 32>>>();   // ncu -s 5 alignment: spn_main at slot 6
    dummy_b_kernel<<<1, 32>>>();
    spn_main<<<dim3(GROUPS / WARPS, NROWS / RB), WARPS * 32>>>(x);
    reduce_kernel<<<NROWS / 8, 256>>>((float*)d_out);
}

// round 15
// speedup vs baseline: 1.0606x; 1.0606x over previous
#include <cuda_runtime.h>
#include <cuda_pipeline.h>

#define F_IN   10000
#define F_PAD  10240     // padded to 80 groups of 128 columns
#define NROWS  4096
#define GROUPS 80        // column groups of 128
#define WARPS  4         // warps per block (one group each)
#define RB     64        // rows per block
#define CH     4         // rows per cp.async chunk
#define NB     4         // chunk buffers (3 in flight)
#define NC     (RB / CH) // chunks per block (16, divisible by 4)
#define NPART  (GROUPS * 8)          // 640 partials per row
#define L2E    1.4426950408889634f
#define LN2    0.6931471805599453f
#define HL2PI2 1.3257480647361593f   // 0.5*log2(2*pi)

// scratch (no allocations allowed)
__device__ float g_pp[F_PAD * 9];               // per-column [m][{-K, B, C_}] base-2 Horner params
__device__ float g_part[(size_t)NROWS * NPART]; // per-row partials, row-major

__device__ __forceinline__ float ex2(float x) {
    float r; asm("ex2.approx.ftz.f32 %0, %1;" : "=f"(r) : "f"(x)); return r;
}
__device__ __forceinline__ float lg2(float x) {
    float r; asm("lg2.approx.ftz.f32 %0, %1;" : "=f"(r) : "f"(x)); return r;
}

// Empty kernels: keep the ncu capture window (-s 5 -c 1) on spn_main.
__global__ void dummy_a_kernel() {}
__global__ void dummy_b_kernel() {}

// Kernel 1: one thread per (f, m). Folds w1 log-softmax, log(std), permutation
// into per-column base-2 Horner constants: t_m(x) = (-K x + B) x + C_.
// Pad columns contribute exactly 0: t0 = 0, t1 = t2 = -1e30 (garbage x is
// harmless there — enables unpredicated clamped loads in the main kernel).
__global__ void prep_kernel(const float* __restrict__ means,
                            const float* __restrict__ stds,
                            const float* __restrict__ w1,
                            const int*   __restrict__ idx) {
    int t = blockIdx.x * blockDim.x + threadIdx.x;
    int f = t / 3, m = t - f * 3;
    if (f >= F_PAD) return;
    if (f >= F_IN) {
        if (m == 0) {
            float* q = &g_pp[(size_t)f * 9];
            q[0]=0.f; q[1]=0.f; q[2]=0.f;
            q[3]=0.f; q[4]=0.f; q[5]=-1e30f;
            q[6]=0.f; q[7]=0.f; q[8]=-1e30f;
        }
        return;
    }
    float u0 = w1[f*3+0]*L2E, u1 = w1[f*3+1]*L2E, u2 = w1[f*3+2]*L2E;
    float mu = fmaxf(u0, fmaxf(u1, u2));
    float l2 = mu + lg2(ex2(u0-mu) + ex2(u1-mu) + ex2(u2-mu));  // log2 softmax denom
    float um   = (m == 0) ? u0 : (m == 1 ? u1 : u2);
    float mean = means[f*3+m];
    float sd   = stds[f*3+m];
    float K    = 0.7213475204444817f / (sd * sd);   // 0.5*log2(e)/sd^2
    float A    = (um - l2) - lg2(sd) - HL2PI2;
    float* q = &g_pp[(size_t)idx[f] * 9 + m * 3];
    q[0] = -K;
    q[1] = 2.0f * K * mean;
    q[2] = A - K * mean * mean;
}

// Kernel 2: R13 body (warp = 128 cols, lane = 4 consecutive cols, 64 regs,
// hoisted output pointer) + QUAD-buffered cp.async: 3 chunks (12 rows) in
// flight per warp, wait_prior(3), compile-time buffer indices via x4 unroll.
// R13 ncu: issue 67.6%, DRAM 55%, 128 cyc/warp-row vs 87-slot floor — the
// residual was wait_prior exposure + too-shallow in-flight depth.
__global__ __launch_bounds__(WARPS * 32) void spn_main(const float* __restrict__ x) {
    const int lane = threadIdx.x & 31;
    const int w    = threadIdx.x >> 5;
    const int g    = blockIdx.x * WARPS + w;      // column group 0..79
    const int r0   = blockIdx.y * RB;
    const int cbase = g * 128 + lane * 4;         // 4 consecutive columns

    __shared__ float4 buf[WARPS][NB][CH][32];     // per-warp quad-buffered chunks

    float nk[4][3], pb[4][3], pc[4][3];
    #pragma unroll
    for (int c = 0; c < 4; c++) {
        const float* p = &g_pp[(size_t)(cbase + c) * 9];
        #pragma unroll
        for (int m = 0; m < 3; m++) {
            nk[c][m] = __ldg(p + m*3 + 0);
            pb[c][m] = __ldg(p + m*3 + 1);
            pc[c][m] = __ldg(p + m*3 + 2);
        }
    }
    // Clamp OOB lanes to a valid address; pad params zero their contribution.
    const int ccl = (cbase < F_IN) ? cbase : (F_IN - 4);
    const float* gp = x + (size_t)r0 * F_IN + ccl;

    float4* sb0 = &buf[w][0][0][lane];   // imm-offset addressing within a buffer
    float4* sb1 = &buf[w][1][0][lane];
    float4* sb2 = &buf[w][2][0][lane];
    float4* sb3 = &buf[w][3][0][lane];
    float4* const sb[NB] = {sb0, sb1, sb2, sb3};

    float* outp = g_part + (size_t)r0 * NPART + g * 8 + lane;
    const bool wr = (lane < 8);

    auto body = [&](float4 xv4) {
        const float xa[4] = {xv4.x, xv4.y, xv4.z, xv4.w};
        float a = 0.0f, p = 1.0f;
        #pragma unroll
        for (int c = 0; c < 4; c++) {
            float xv = xa[c];
            float t0 = fmaf(fmaf(xv, nk[c][0], pb[c][0]), xv, pc[c][0]);
            float t1 = fmaf(fmaf(xv, nk[c][1], pb[c][1]), xv, pc[c][1]);
            float t2 = fmaf(fmaf(xv, nk[c][2], pb[c][2]), xv, pc[c][2]);
            float hi = fmaxf(t0, t1), lo = fminf(t0, t1);
            float mx = fmaxf(hi, t2), md = fminf(hi, t2);
            float s  = ex2(md - mx) + ex2(lo - mx);
            a += mx;
            p = fmaf(s, p, p);     // p *= (1 + s); p <= 3^4 per lane
        }
        a += __shfl_xor_sync(0xffffffffu, a, 16);
        p *= __shfl_xor_sync(0xffffffffu, p, 16);
        a += __shfl_xor_sync(0xffffffffu, a, 8);
        p *= __shfl_xor_sync(0xffffffffu, p, 8);
        float v = a + lg2(p);      // product of 4 lanes <= 3^16, no overflow
        if (wr) *outp = v;
        outp += NPART;
    };

    // Prologue: chunks 0..2 in flight (one commit group each).
    #pragma unroll
    for (int q = 0; q < NB - 1; q++) {
        #pragma unroll
        for (int i = 0; i < CH; i++)
            __pipeline_memcpy_async(sb[q] + i * 32, gp + (size_t)i * F_IN, 16);
        __pipeline_commit();
        gp += (size_t)CH * F_IN;
    }

    #pragma unroll 1
    for (int k = 0; k < NC; k += NB) {
        #pragma unroll
        for (int j = 0; j < NB; j++) {
            // Issue chunk k+j+3 into buffer (j+3)&3, then wait for chunk k+j.
            if (k + j + (NB - 1) < NC) {
                float4* dst = sb[(j + NB - 1) & (NB - 1)];
                #pragma unroll
                for (int i = 0; i < CH; i++)
                    __pipeline_memcpy_async(dst + i * 32, gp + (size_t)i * F_IN, 16);
                gp += (size_t)CH * F_IN;
            }
            __pipeline_commit();           // (possibly empty group keeps counts aligned)
            __pipeline_wait_prior(NB - 1); // chunk k+j complete
            #pragma unroll
            for (int i = 0; i < CH; i++) body(sb[j][i * 32]);
        }
    }
}

// Kernel 3: fold 640 partials per row (one warp per row, float4 loads).
__global__ void reduce_kernel(float* __restrict__ out) {
    const int lane = threadIdx.x & 31;
    const int n    = blockIdx.x * (blockDim.x >> 5) + (threadIdx.x >> 5);
    if (n >= NROWS) return;
    const float4* p4 = (const float4*)&g_part[(size_t)n * NPART];  // 160 float4s
    float s = 0.0f;
    #pragma unroll
    for (int i = 0; i < NPART / 128; i++) {   // 5 iterations
        float4 v = p4[lane + i * 32];
        s += (v.x + v.y) + (v.z + v.w);
    }
    #pragma unroll
    for (int off = 16; off; off >>= 1)
        s += __shfl_xor_sync(0xffffffffu, s, off);
    if (lane == 0) out[n] = s * LN2;
}

extern "C" void kernel_launch(void* const* d_in, const int* in_sizes, int n_in,
                              void* d_out, int out_size) {
    const float* x     = (const float*)d_in[0];
    const float* means = (const float*)d_in[1];
    const float* stds  = (const float*)d_in[2];
    const float* w1    = (const float*)d_in[3];
    // d_in[4..7] = w2..w5: provably no-ops (log_softmax over size-1 axis == 0)
    const int*   idx   = (const int*)d_in[8];

    prep_kernel<<<(F_PAD * 3 + 127) / 128, 128>>>(means, stds, w1, idx);
    dummy_a_kernel<<<1, 32>>>();   // ncu -s 5 alignment: spn_main at slot 6
    dummy_b_kernel<<<1, 32>>>();
    spn_main<<<dim3(GROUPS / WARPS, NROWS / RB), WARPS * 32>>>(x);
    reduce_kernel<<<NROWS / 8, 256>>>((float*)d_out);
}